// round 15
// baseline (speedup 1.0000x reference)
#include <cuda_runtime.h>
#include <math.h>

// ---------------- problem constants ----------------
#define Bn   64
#define Tn   512
#define Dn   64
#define Fn   64
#define Un   128
#define Mn   256          // 2*U
#define NHn  4
#define KDn  128
#define Gn   384          // 3*U
#define BTn  (Bn*Tn)      // 32768

// ---------------- device scratch (no allocs allowed) ----------------
__device__ float g_x1 [BTn*Fn];             // conv output
__device__ float g_xgf[BTn*Gn];             // xg forward (reused)
__device__ float g_xgb[BTn*Gn];             // xg backward (reused)
__device__ float g_y1 [BTn*Mn];             // GRU1 sequence out
__device__ float g_q  [Bn*NHn*Tn*KDn];      // Q [B,NH,T,KD]
__device__ float g_k  [Bn*NHn*Tn*KDn];      // K / x2 [BT,M]
__device__ float g_v  [Bn*NHn*Tn*KDn];      // V
__device__ float g_o  [BTn*NHn*KDn];        // attention out [B,T,NH,KD]
__device__ float g_h2 [Bn*Mn];              // GRU2 final states

// ---------------- helpers ----------------
__device__ __forceinline__ float to_tf32(float x) {
    asm("cvt.rna.tf32.f32 %0, %0;" : "+f"(x));
    return x;
}
__device__ __forceinline__ void mma_tf32(float* d,
    unsigned a0, unsigned a1, unsigned a2, unsigned a3,
    unsigned b0, unsigned b1)
{
    asm volatile(
        "mma.sync.aligned.m16n8k8.row.col.f32.tf32.tf32.f32 "
        "{%0,%1,%2,%3}, {%4,%5,%6,%7}, {%8,%9}, {%0,%1,%2,%3};\n"
        : "+f"(d[0]), "+f"(d[1]), "+f"(d[2]), "+f"(d[3])
        : "r"(a0), "r"(a1), "r"(a2), "r"(a3), "r"(b0), "r"(b1));
}
__device__ __forceinline__ float fsig(float x) {
    x = fminf(fmaxf(x, -30.f), 30.f);
    return __fdividef(1.f, 1.f + __expf(-x));
}
__device__ __forceinline__ float ftanh(float x) {
    x = fminf(fmaxf(x, -15.f), 15.f);
    float e = __expf(2.f * x);
    return __fdividef(e - 1.f, e + 1.f);
}

// ---------------- conv1d(same,w=3) + BN(eps=1e-3) + ReLU ----------------
__global__ void conv_bn_relu(const float* __restrict__ x,
                             const float* __restrict__ w,
                             const float* __restrict__ cb,
                             const float* __restrict__ gamma,
                             const float* __restrict__ beta,
                             const float* __restrict__ mean,
                             const float* __restrict__ var)
{
    int idx = blockIdx.x * blockDim.x + threadIdx.x;
    if (idx >= BTn * Fn) return;
    int f = idx & 63;
    int t = (idx >> 6) & 511;
    int b = idx >> 15;
    float acc = cb[f];
    #pragma unroll
    for (int kk = 0; kk < 3; kk++) {
        int tt = t + kk - 1;
        if (tt < 0 || tt >= Tn) continue;
        const float* row = x + ((long long)b * Tn + tt) * Dn;
        const float* wr  = w + kk * Dn * Fn + f;
        #pragma unroll
        for (int d = 0; d < Dn; d++)
            acc = fmaf(row[d], wr[d * Fn], acc);
    }
    acc = (acc - mean[f]) * rsqrtf(var[f] + 1e-3f) * gamma[f] + beta[f];
    g_x1[idx] = fmaxf(acc, 0.f);
}

// ---------------- tf32 tensor-core GEMM (64x64 tile) ----------------
// TRB=true : B stored [N,K] row-major (computes A @ B^T)
// EPI: 0 = plain row-major; 1 = QKV permute.
template<int EPI, bool TRB>
__global__ void __launch_bounds__(256)
gemm_tf32(const float* __restrict__ A, const float* __restrict__ Bm,
          float* __restrict__ C, int N, int K,
          const float* __restrict__ bias, const float* __restrict__ resid,
          long long sA, long long sB, long long sC, float alpha)
{
    __shared__ float As[64][20];
    __shared__ float Bs[16][72];

    int tid  = threadIdx.x;
    int lane = tid & 31;
    int wid  = tid >> 5;
    int wm   = wid >> 1;
    int wn   = wid & 1;
    int g    = lane >> 2;
    int c    = lane & 3;
    int m0 = blockIdx.y << 6, n0 = blockIdx.x << 6, z = blockIdx.z;
    A  += (long long)z * sA;
    Bm += (long long)z * sB;

    float acc[4][4] = {};

    int a_r = tid >> 2, a_c = (tid & 3) << 2;
    int b_r = tid >> 4, b_c = (tid & 15) << 2;

    float4 ar = *(const float4*)&A[(long long)(m0 + a_r) * K + a_c];
    float4 br;
    if (TRB) br = *(const float4*)&Bm[(long long)(n0 + a_r) * K + a_c];
    else     br = *(const float4*)&Bm[(long long)b_r * N + n0 + b_c];

    for (int k0 = 0; k0 < K; k0 += 16) {
        float4 at; at.x = to_tf32(ar.x); at.y = to_tf32(ar.y);
                   at.z = to_tf32(ar.z); at.w = to_tf32(ar.w);
        *(float4*)&As[a_r][a_c] = at;
        if (TRB) {
            Bs[a_c + 0][a_r] = to_tf32(br.x);
            Bs[a_c + 1][a_r] = to_tf32(br.y);
            Bs[a_c + 2][a_r] = to_tf32(br.z);
            Bs[a_c + 3][a_r] = to_tf32(br.w);
        } else {
            float4 bt; bt.x = to_tf32(br.x); bt.y = to_tf32(br.y);
                       bt.z = to_tf32(br.z); bt.w = to_tf32(br.w);
            *(float4*)&Bs[b_r][b_c] = bt;
        }
        __syncthreads();

        if (k0 + 16 < K) {
            ar = *(const float4*)&A[(long long)(m0 + a_r) * K + k0 + 16 + a_c];
            if (TRB) br = *(const float4*)&Bm[(long long)(n0 + a_r) * K + k0 + 16 + a_c];
            else     br = *(const float4*)&Bm[(long long)(k0 + 16 + b_r) * N + n0 + b_c];
        }

        #pragma unroll
        for (int kk = 0; kk < 16; kk += 8) {
            unsigned a0 = __float_as_uint(As[wm * 16 + g    ][kk + c    ]);
            unsigned a1 = __float_as_uint(As[wm * 16 + g + 8][kk + c    ]);
            unsigned a2 = __float_as_uint(As[wm * 16 + g    ][kk + c + 4]);
            unsigned a3 = __float_as_uint(As[wm * 16 + g + 8][kk + c + 4]);
            #pragma unroll
            for (int nt = 0; nt < 4; nt++) {
                int ncol = wn * 32 + nt * 8 + g;
                unsigned b0 = __float_as_uint(Bs[kk + c    ][ncol]);
                unsigned b1 = __float_as_uint(Bs[kk + c + 4][ncol]);
                mma_tf32(acc[nt], a0, a1, a2, a3, b0, b1);
            }
        }
        __syncthreads();
    }

    #pragma unroll
    for (int nt = 0; nt < 4; nt++) {
        #pragma unroll
        for (int i = 0; i < 4; i++) {
            int row = m0 + wm * 16 + g + ((i >> 1) << 3);
            int col = n0 + wn * 32 + nt * 8 + (c << 1) + (i & 1);
            float v = acc[nt][i] * alpha;
            if (bias) v += bias[col];
            if (EPI == 0) {
                long long off = (long long)z * sC + (long long)row * N + col;
                if (resid) v += resid[(long long)row * N + col];
                C[off] = v;
            } else {
                int b = row >> 9, t = row & 511;
                int h = col >> 7, k = col & 127;
                C[(((long long)b * NHn + h) * Tn + t) * KDn + k] = v;
            }
        }
    }
}

// ---------------- flash attention (tf32 mma, online softmax) ----------------
// grid (T/128, B*NH), 256 threads. Warp w owns Q rows [w*16, w*16+16) and their
// full softmax stats (warp-local shuffles only). K loop over 8 tiles of 64.
__global__ void __launch_bounds__(256, 1)
flash_attn(const float* __restrict__ Qg, const float* __restrict__ Kg,
           const float* __restrict__ Vg, float* __restrict__ Og)
{
    extern __shared__ float sm[];
    float (*Qs)[132] = (float(*)[132])sm;                                // 128x128 kd
    float (*Ks)[140] = (float(*)[140])(sm + 128*132);                    // 64 seq x 128 kd
    float (*Vs)[136] = (float(*)[136])(sm + 128*132 + 64*140);           // 64 seq x 128 kd
    float (*Ps)[76]  = (float(*)[76]) (sm + 128*132 + 64*140 + 64*136);  // 128 q x 64 seq

    int tid = threadIdx.x, lane = tid & 31, wid = tid >> 5;
    int g = lane >> 2, c = lane & 3;
    int bh  = blockIdx.y;
    int t0q = blockIdx.x << 7;
    const float scale = 0.08838834764831845f;   // 1/sqrt(128)

    const float* Qp = Qg + ((long long)bh * Tn + t0q) * KDn;
    const float* Kp = Kg + (long long)bh * Tn * KDn;
    const float* Vp = Vg + (long long)bh * Tn * KDn;

    // load Q tile (pre-scaled, tf32)
    for (int idx = tid; idx < 128 * 32; idx += 256) {
        int r = idx >> 5, k4 = (idx & 31) << 2;
        float4 qv = *(const float4*)&Qp[(long long)r * KDn + k4];
        Qs[r][k4+0] = to_tf32(qv.x * scale);
        Qs[r][k4+1] = to_tf32(qv.y * scale);
        Qs[r][k4+2] = to_tf32(qv.z * scale);
        Qs[r][k4+3] = to_tf32(qv.w * scale);
    }

    int wrow = wid << 4;
    float oacc[16][4];
    #pragma unroll
    for (int i = 0; i < 16; i++)
        oacc[i][0] = oacc[i][1] = oacc[i][2] = oacc[i][3] = 0.f;
    float m0 = -1e30f, m1 = -1e30f, l0 = 0.f, l1 = 0.f;

    for (int t0k = 0; t0k < Tn; t0k += 64) {
        __syncthreads();            // previous PV mma done reading Ks/Vs
        for (int idx = tid; idx < 64 * 32; idx += 256) {
            int r = idx >> 5, k4 = (idx & 31) << 2;
            float4 kv = *(const float4*)&Kp[(long long)(t0k + r) * KDn + k4];
            float4 vv = *(const float4*)&Vp[(long long)(t0k + r) * KDn + k4];
            Ks[r][k4+0] = to_tf32(kv.x); Ks[r][k4+1] = to_tf32(kv.y);
            Ks[r][k4+2] = to_tf32(kv.z); Ks[r][k4+3] = to_tf32(kv.w);
            Vs[r][k4+0] = to_tf32(vv.x); Vs[r][k4+1] = to_tf32(vv.y);
            Vs[r][k4+2] = to_tf32(vv.z); Vs[r][k4+3] = to_tf32(vv.w);
        }
        __syncthreads();

        // S = Q @ K^T for this warp's 16 rows x 64 cols
        float sacc[8][4] = {};
        #pragma unroll
        for (int kk = 0; kk < 128; kk += 8) {
            unsigned a0 = __float_as_uint(Qs[wrow + g    ][kk + c    ]);
            unsigned a1 = __float_as_uint(Qs[wrow + g + 8][kk + c    ]);
            unsigned a2 = __float_as_uint(Qs[wrow + g    ][kk + c + 4]);
            unsigned a3 = __float_as_uint(Qs[wrow + g + 8][kk + c + 4]);
            #pragma unroll
            for (int nt = 0; nt < 8; nt++) {
                int n = (nt << 3) + g;
                unsigned b0 = __float_as_uint(Ks[n][kk + c    ]);
                unsigned b1 = __float_as_uint(Ks[n][kk + c + 4]);
                mma_tf32(sacc[nt], a0, a1, a2, a3, b0, b1);
            }
        }

        // online softmax: thread holds rows {g, g+8}, cols {2c,2c+1} per ntile
        float rm0 = -1e30f, rm1 = -1e30f;
        #pragma unroll
        for (int nt = 0; nt < 8; nt++) {
            rm0 = fmaxf(rm0, fmaxf(sacc[nt][0], sacc[nt][1]));
            rm1 = fmaxf(rm1, fmaxf(sacc[nt][2], sacc[nt][3]));
        }
        rm0 = fmaxf(rm0, __shfl_xor_sync(0xffffffffu, rm0, 1));
        rm0 = fmaxf(rm0, __shfl_xor_sync(0xffffffffu, rm0, 2));
        rm1 = fmaxf(rm1, __shfl_xor_sync(0xffffffffu, rm1, 1));
        rm1 = fmaxf(rm1, __shfl_xor_sync(0xffffffffu, rm1, 2));
        float mn0 = fmaxf(m0, rm0), mn1 = fmaxf(m1, rm1);
        float cor0 = __expf(m0 - mn0), cor1 = __expf(m1 - mn1);
        float rs0 = 0.f, rs1 = 0.f;
        #pragma unroll
        for (int nt = 0; nt < 8; nt++) {
            float p0 = __expf(sacc[nt][0] - mn0);
            float p1 = __expf(sacc[nt][1] - mn0);
            float p2 = __expf(sacc[nt][2] - mn1);
            float p3 = __expf(sacc[nt][3] - mn1);
            rs0 += p0 + p1; rs1 += p2 + p3;
            int col = (nt << 3) + (c << 1);
            Ps[wrow + g    ][col]     = to_tf32(p0);
            Ps[wrow + g    ][col + 1] = to_tf32(p1);
            Ps[wrow + g + 8][col]     = to_tf32(p2);
            Ps[wrow + g + 8][col + 1] = to_tf32(p3);
        }
        rs0 += __shfl_xor_sync(0xffffffffu, rs0, 1);
        rs0 += __shfl_xor_sync(0xffffffffu, rs0, 2);
        rs1 += __shfl_xor_sync(0xffffffffu, rs1, 1);
        rs1 += __shfl_xor_sync(0xffffffffu, rs1, 2);
        l0 = l0 * cor0 + rs0; l1 = l1 * cor1 + rs1;
        m0 = mn0; m1 = mn1;
        #pragma unroll
        for (int nt = 0; nt < 16; nt++) {
            oacc[nt][0] *= cor0; oacc[nt][1] *= cor0;
            oacc[nt][2] *= cor1; oacc[nt][3] *= cor1;
        }
        __syncwarp();   // Ps rows are warp-private: warp-level ordering suffices

        // O += P @ V   (contraction over the 64 seq cols)
        #pragma unroll
        for (int kk = 0; kk < 64; kk += 8) {
            unsigned a0 = __float_as_uint(Ps[wrow + g    ][kk + c    ]);
            unsigned a1 = __float_as_uint(Ps[wrow + g + 8][kk + c    ]);
            unsigned a2 = __float_as_uint(Ps[wrow + g    ][kk + c + 4]);
            unsigned a3 = __float_as_uint(Ps[wrow + g + 8][kk + c + 4]);
            #pragma unroll
            for (int nt = 0; nt < 16; nt++) {
                int n = (nt << 3) + g;
                unsigned b0 = __float_as_uint(Vs[kk + c    ][n]);
                unsigned b1 = __float_as_uint(Vs[kk + c + 4][n]);
                mma_tf32(oacc[nt], a0, a1, a2, a3, b0, b1);
            }
        }
        __syncwarp();
    }

    // epilogue: divide by l, write O in [B,T,NH,KD]
    int b = bh >> 2, h = bh & 3;
    float inv0 = __fdividef(1.f, l0), inv1 = __fdividef(1.f, l1);
    int r0 = t0q + wrow + g, r1 = r0 + 8;
    long long base0 = (((long long)b * Tn + r0) * NHn + h) * KDn;
    long long base1 = (((long long)b * Tn + r1) * NHn + h) * KDn;
    #pragma unroll
    for (int nt = 0; nt < 16; nt++) {
        int col = (nt << 3) + (c << 1);
        Og[base0 + col]     = oacc[nt][0] * inv0;
        Og[base0 + col + 1] = oacc[nt][1] * inv0;
        Og[base1 + col]     = oacc[nt][2] * inv1;
        Og[base1 + col + 1] = oacc[nt][3] * inv1;
    }
}

// ---------------- persistent bidirectional GRU layer ----------------
// grid = B*2 CTAs; block = 384 threads; thread j owns gate column j,
// wh column cached in 128 registers. xv prefetched one step ahead.
__global__ void __launch_bounds__(384, 1)
gru_layer(const float* __restrict__ xgf, const float* __restrict__ xgb,
          const float* __restrict__ whf, const float* __restrict__ whb,
          const float* __restrict__ bhf, const float* __restrict__ bhb,
          float* __restrict__ yseq, float* __restrict__ hfin)
{
    int b   = blockIdx.x >> 1;
    int dir = blockIdx.x & 1;
    const float* xg = dir ? xgb : xgf;
    const float* wh = dir ? whb : whf;
    const float* bh = dir ? bhb : bhf;
    int j = threadIdx.x;

    __shared__ float4 h4s[32];       // hidden state h[128]
    __shared__ float  gate[256];     // z, r exchange
    float* h = (float*)h4s;

    float w[128];
    #pragma unroll
    for (int u = 0; u < 128; u++) w[u] = wh[u * Gn + j];
    float bj = bh[j];
    if (j < 128) h[j] = 0.f;
    __syncthreads();

    const float* xbase = xg + (long long)b * Tn * Gn;
    int t0 = dir ? (Tn - 1) : 0;
    float xv = xbase[(long long)t0 * Gn + j];

    for (int s = 0; s < Tn; s++) {
        int t  = dir ? (Tn - 1 - s) : s;
        int tn = dir ? (Tn - 2 - s) : (s + 1);
        // prefetch next step's xv: its latency hides under this step's FMA loop
        float xv_next = (s + 1 < Tn) ? xbase[(long long)tn * Gn + j] : 0.f;

        float a0 = 0.f, a1 = 0.f, a2 = 0.f, a3 = 0.f;
        #pragma unroll
        for (int u = 0; u < 32; u++) {
            float4 hv = h4s[u];
            a0 = fmaf(hv.x, w[4 * u + 0], a0);
            a1 = fmaf(hv.y, w[4 * u + 1], a1);
            a2 = fmaf(hv.z, w[4 * u + 2], a2);
            a3 = fmaf(hv.w, w[4 * u + 3], a3);
        }
        float acc = (a0 + a1) + (a2 + a3) + bj;      // (h @ wh + bh)[j]
        if (j < 256)
            gate[j] = fsig(xv + acc);
        __syncthreads();
        if (j >= 256) {
            int u = j - 256;
            float r = gate[128 + u];
            float n = ftanh(xv + r * acc);
            float z = gate[u];
            float hn = z * h[u] + (1.f - z) * n;
            h[u] = hn;
            if (yseq)
                yseq[((long long)b * Tn + t) * Mn + dir * Un + u] = hn;
        }
        __syncthreads();
        xv = xv_next;
    }
    if (hfin && j < 128)
        hfin[b * Mn + dir * Un + j] = h[j];
}

// ---------------- final dense head [B,256] @ [256,1] ----------------
__global__ void dense_head(const float* __restrict__ h2, const float* __restrict__ w,
                           const float* __restrict__ bb, float* __restrict__ out)
{
    int b = blockIdx.x, tid = threadIdx.x;   // 256 threads
    __shared__ float red[256];
    red[tid] = h2[b * Mn + tid] * w[tid];
    __syncthreads();
    #pragma unroll
    for (int o = 128; o > 0; o >>= 1) {
        if (tid < o) red[tid] += red[tid + o];
        __syncthreads();
    }
    if (tid == 0) out[b] = red[0] + bb[0];
}

// ---------------- launch orchestration ----------------
extern "C" void kernel_launch(void* const* d_in, const int* in_sizes, int n_in,
                              void* d_out, int out_size)
{
    const float* inp     = (const float*)d_in[0];
    const float* conv_w  = (const float*)d_in[1];
    const float* conv_b  = (const float*)d_in[2];
    const float* bn_g    = (const float*)d_in[3];
    const float* bn_b    = (const float*)d_in[4];
    const float* bn_m    = (const float*)d_in[5];
    const float* bn_v    = (const float*)d_in[6];
    const float* g1f_wx  = (const float*)d_in[7];
    const float* g1f_wh  = (const float*)d_in[8];
    const float* g1f_b   = (const float*)d_in[9];
    const float* g1b_wx  = (const float*)d_in[10];
    const float* g1b_wh  = (const float*)d_in[11];
    const float* g1b_b   = (const float*)d_in[12];
    const float* wq      = (const float*)d_in[13];
    const float* bq      = (const float*)d_in[14];
    const float* wk      = (const float*)d_in[15];
    const float* bk      = (const float*)d_in[16];
    const float* wv      = (const float*)d_in[17];
    const float* bv      = (const float*)d_in[18];
    const float* wo      = (const float*)d_in[19];
    const float* bo      = (const float*)d_in[20];
    const float* g2f_wx  = (const float*)d_in[21];
    const float* g2f_wh  = (const float*)d_in[22];
    const float* g2f_b   = (const float*)d_in[23];
    const float* g2b_wx  = (const float*)d_in[24];
    const float* g2b_wh  = (const float*)d_in[25];
    const float* g2b_b   = (const float*)d_in[26];
    const float* dense_w = (const float*)d_in[27];
    const float* dense_b = (const float*)d_in[28];
    float* out = (float*)d_out;

    float *x1, *xgf, *xgb, *y1, *q, *k, *v, *o, *h2;
    cudaGetSymbolAddress((void**)&x1,  g_x1);
    cudaGetSymbolAddress((void**)&xgf, g_xgf);
    cudaGetSymbolAddress((void**)&xgb, g_xgb);
    cudaGetSymbolAddress((void**)&y1,  g_y1);
    cudaGetSymbolAddress((void**)&q,   g_q);
    cudaGetSymbolAddress((void**)&k,   g_k);
    cudaGetSymbolAddress((void**)&v,   g_v);
    cudaGetSymbolAddress((void**)&o,   g_o);
    cudaGetSymbolAddress((void**)&h2,  g_h2);

    // flash_attn needs ~173 KB dynamic smem (idempotent host call; not captured)
    const int FA_SMEM = (128*132 + 64*140 + 64*136 + 128*76) * 4;
    cudaFuncSetAttribute(flash_attn, cudaFuncAttributeMaxDynamicSharedMemorySize, FA_SMEM);

    dim3 blk(256);

    // 1) conv + BN + ReLU -> x1 [BT, F]
    conv_bn_relu<<<(BTn * Fn) / 256, 256>>>(inp, conv_w, conv_b, bn_g, bn_b, bn_m, bn_v);

    // 2) GRU1 input projections
    gemm_tf32<0,false><<<dim3(Gn/64, BTn/64, 1), blk>>>(x1, g1f_wx, xgf, Gn, Fn, g1f_b, nullptr, 0,0,0, 1.f);
    gemm_tf32<0,false><<<dim3(Gn/64, BTn/64, 1), blk>>>(x1, g1b_wx, xgb, Gn, Fn, g1b_b, nullptr, 0,0,0, 1.f);

    // 3) bidirectional GRU1 -> y1 [BT, 256]
    gru_layer<<<Bn * 2, 384>>>(xgf, xgb, g1f_wh, g1b_wh, g1f_b + Gn, g1b_b + Gn, y1, nullptr);

    // 4) QKV projections -> [B,NH,T,KD]
    gemm_tf32<1,false><<<dim3(512/64, BTn/64, 1), blk>>>(y1, wq, q, NHn*KDn, Mn, bq, nullptr, 0,0,0, 1.f);
    gemm_tf32<1,false><<<dim3(512/64, BTn/64, 1), blk>>>(y1, wk, k, NHn*KDn, Mn, bk, nullptr, 0,0,0, 1.f);
    gemm_tf32<1,false><<<dim3(512/64, BTn/64, 1), blk>>>(y1, wv, v, NHn*KDn, Mn, bv, nullptr, 0,0,0, 1.f);

    // 5-7) fused attention: scores + softmax + PV, out -> g_o [B,T,NH,KD]
    flash_attn<<<dim3(Tn/128, Bn*NHn), blk, FA_SMEM>>>(q, k, v, o);

    // 8) x2 = y1 + O @ wo + bo  -> k buffer [BT, 256]
    gemm_tf32<0,false><<<dim3(Mn/64, BTn/64, 1), blk>>>(o, wo, k, Mn, NHn*KDn, bo, y1, 0,0,0, 1.f);

    // 9) GRU2 input projections (reuse xgf/xgb)
    gemm_tf32<0,false><<<dim3(Gn/64, BTn/64, 1), blk>>>(k, g2f_wx, xgf, Gn, Mn, g2f_b, nullptr, 0,0,0, 1.f);
    gemm_tf32<0,false><<<dim3(Gn/64, BTn/64, 1), blk>>>(k, g2b_wx, xgb, Gn, Mn, g2b_b, nullptr, 0,0,0, 1.f);

    // 10) bidirectional GRU2 (final states only) -> h2 [B, 256]
    gru_layer<<<Bn * 2, 384>>>(xgf, xgb, g2f_wh, g2b_wh, g2f_b + Gn, g2b_b + Gn, nullptr, h2);

    // 11) dense head -> out [B, 1]
    dense_head<<<Bn, 256>>>(h2, dense_w, dense_b, out);
}

// round 16
// speedup vs baseline: 1.0621x; 1.0621x over previous
#include <cuda_runtime.h>
#include <math.h>

// ---------------- problem constants ----------------
#define Bn   64
#define Tn   512
#define Dn   64
#define Fn   64
#define Un   128
#define Mn   256          // 2*U
#define NHn  4
#define KDn  128
#define Gn   384          // 3*U
#define BTn  (Bn*Tn)      // 32768

// ---------------- device scratch (no allocs allowed) ----------------
__device__ float g_x1 [BTn*Fn];             // conv output
__device__ float g_xgf[BTn*Gn];             // xg forward (reused)
__device__ float g_xgb[BTn*Gn];             // xg backward (reused)
__device__ float g_y1 [BTn*Mn];             // GRU1 sequence out
__device__ float g_q  [Bn*NHn*Tn*KDn];      // Q [B,NH,T,KD]
__device__ float g_k  [Bn*NHn*Tn*KDn];      // K / x2 [BT,M]
__device__ float g_v  [Bn*NHn*Tn*KDn];      // V
__device__ float g_o  [BTn*NHn*KDn];        // attention out [B,T,NH,KD]
__device__ float g_h2 [Bn*Mn];              // GRU2 final states

// ---------------- helpers ----------------
__device__ __forceinline__ float to_tf32(float x) {
    asm("cvt.rna.tf32.f32 %0, %0;" : "+f"(x));
    return x;
}
__device__ __forceinline__ void mma_tf32(float* d,
    unsigned a0, unsigned a1, unsigned a2, unsigned a3,
    unsigned b0, unsigned b1)
{
    asm volatile(
        "mma.sync.aligned.m16n8k8.row.col.f32.tf32.tf32.f32 "
        "{%0,%1,%2,%3}, {%4,%5,%6,%7}, {%8,%9}, {%0,%1,%2,%3};\n"
        : "+f"(d[0]), "+f"(d[1]), "+f"(d[2]), "+f"(d[3])
        : "r"(a0), "r"(a1), "r"(a2), "r"(a3), "r"(b0), "r"(b1));
}
__device__ __forceinline__ float fsig(float x) {
    x = fminf(fmaxf(x, -30.f), 30.f);
    return __fdividef(1.f, 1.f + __expf(-x));
}
__device__ __forceinline__ float ftanh(float x) {
    x = fminf(fmaxf(x, -15.f), 15.f);
    float e = __expf(2.f * x);
    return __fdividef(e - 1.f, e + 1.f);
}

// ---------------- conv1d(same,w=3) + BN(eps=1e-3) + ReLU ----------------
__global__ void conv_bn_relu(const float* __restrict__ x,
                             const float* __restrict__ w,
                             const float* __restrict__ cb,
                             const float* __restrict__ gamma,
                             const float* __restrict__ beta,
                             const float* __restrict__ mean,
                             const float* __restrict__ var)
{
    int idx = blockIdx.x * blockDim.x + threadIdx.x;
    if (idx >= BTn * Fn) return;
    int f = idx & 63;
    int t = (idx >> 6) & 511;
    int b = idx >> 15;
    float acc = cb[f];
    #pragma unroll
    for (int kk = 0; kk < 3; kk++) {
        int tt = t + kk - 1;
        if (tt < 0 || tt >= Tn) continue;
        const float* row = x + ((long long)b * Tn + tt) * Dn;
        const float* wr  = w + kk * Dn * Fn + f;
        #pragma unroll
        for (int d = 0; d < Dn; d++)
            acc = fmaf(row[d], wr[d * Fn], acc);
    }
    acc = (acc - mean[f]) * rsqrtf(var[f] + 1e-3f) * gamma[f] + beta[f];
    g_x1[idx] = fmaxf(acc, 0.f);
}

// ---------------- tf32 tensor-core GEMM, 128x64 tile, double-buffered ----------------
// 256 threads = 8 warps in 4(m) x 2(n); warp tile 32x32 = 2x4 m16n8k8 tiles.
// ONE __syncthreads per K-step (ping-pong smem: iter i+2's store to buffer p is
// ordered after iter i's reads of p by iter i+1's barrier).
// grid.z selects among up to 3 (B, bias, C) sets so sibling GEMMs share a launch.
// EPI: 0 = plain row-major (+optional resid); 1 = QKV permute to [B,NH,T,KD].
template<int EPI>
__global__ void __launch_bounds__(256)
gemm_tf32(const float* __restrict__ A,
          const float* B0, const float* B1, const float* B2,
          float* C0, float* C1, float* C2,
          int N, int K,
          const float* bias0, const float* bias1, const float* bias2,
          const float* __restrict__ resid)
{
    __shared__ float As[2][128][20];   // pad 20 -> bank spread {0,20,8,28,16,4,24,12}
    __shared__ float Bs[2][16][72];    // pad 72 -> c*8+g covers all banks

    int z = blockIdx.z;
    const float* Bm   = (z == 0) ? B0 : (z == 1) ? B1 : B2;
    const float* bias = (z == 0) ? bias0 : (z == 1) ? bias1 : bias2;
    float*       C    = (z == 0) ? C0 : (z == 1) ? C1 : C2;

    int tid  = threadIdx.x;
    int lane = tid & 31;
    int wid  = tid >> 5;
    int wm   = wid >> 1;                 // 0..3 -> m offset wm*32
    int wn   = wid & 1;                  // 0..1 -> n offset wn*32
    int g    = lane >> 2;                // 0..7
    int c    = lane & 3;                 // 0..3
    int m0 = blockIdx.y << 7, n0 = blockIdx.x << 6;

    float acc[2][4][4] = {};

    int a_r = tid >> 2;                  // 0..63
    int a_c = (tid & 3) << 2;
    int b_r = tid >> 4, b_c = (tid & 15) << 2;

    const float* Ap0 = &A[(long long)(m0 + a_r) * K + a_c];
    const float* Ap1 = &A[(long long)(m0 + a_r + 64) * K + a_c];

    float4 ar0 = *(const float4*)Ap0;
    float4 ar1 = *(const float4*)Ap1;
    float4 br  = *(const float4*)&Bm[(long long)b_r * N + n0 + b_c];

    int nk = K >> 4;
    for (int it = 0; it < nk; it++) {
        int pb = it & 1;
        float4 t0, t1, bt;
        t0.x = to_tf32(ar0.x); t0.y = to_tf32(ar0.y); t0.z = to_tf32(ar0.z); t0.w = to_tf32(ar0.w);
        t1.x = to_tf32(ar1.x); t1.y = to_tf32(ar1.y); t1.z = to_tf32(ar1.z); t1.w = to_tf32(ar1.w);
        bt.x = to_tf32(br.x);  bt.y = to_tf32(br.y);  bt.z = to_tf32(br.z);  bt.w = to_tf32(br.w);
        *(float4*)&As[pb][a_r     ][a_c] = t0;
        *(float4*)&As[pb][a_r + 64][a_c] = t1;
        *(float4*)&Bs[pb][b_r][b_c]      = bt;
        __syncthreads();

        if (it + 1 < nk) {
            int k0 = (it + 1) << 4;
            ar0 = *(const float4*)(Ap0 + k0);
            ar1 = *(const float4*)(Ap1 + k0);
            br  = *(const float4*)&Bm[(long long)(k0 + b_r) * N + n0 + b_c];
        }

        #pragma unroll
        for (int kk = 0; kk < 16; kk += 8) {
            unsigned af[2][4];
            #pragma unroll
            for (int mt = 0; mt < 2; mt++) {
                int rb = wm * 32 + mt * 16;
                af[mt][0] = __float_as_uint(As[pb][rb + g    ][kk + c    ]);
                af[mt][1] = __float_as_uint(As[pb][rb + g + 8][kk + c    ]);
                af[mt][2] = __float_as_uint(As[pb][rb + g    ][kk + c + 4]);
                af[mt][3] = __float_as_uint(As[pb][rb + g + 8][kk + c + 4]);
            }
            #pragma unroll
            for (int nt = 0; nt < 4; nt++) {
                int ncol = wn * 32 + nt * 8 + g;
                unsigned b0 = __float_as_uint(Bs[pb][kk + c    ][ncol]);
                unsigned b1 = __float_as_uint(Bs[pb][kk + c + 4][ncol]);
                mma_tf32(acc[0][nt], af[0][0], af[0][1], af[0][2], af[0][3], b0, b1);
                mma_tf32(acc[1][nt], af[1][0], af[1][1], af[1][2], af[1][3], b0, b1);
            }
        }
    }

    #pragma unroll
    for (int mt = 0; mt < 2; mt++) {
        #pragma unroll
        for (int nt = 0; nt < 4; nt++) {
            #pragma unroll
            for (int i = 0; i < 4; i++) {
                int row = m0 + wm * 32 + mt * 16 + g + ((i >> 1) << 3);
                int col = n0 + wn * 32 + nt * 8 + (c << 1) + (i & 1);
                float v = acc[mt][nt][i];
                if (bias) v += bias[col];
                if (EPI == 0) {
                    long long off = (long long)row * N + col;
                    if (resid) v += resid[off];
                    C[off] = v;
                } else {
                    int b = row >> 9, t = row & 511;
                    int h = col >> 7, kx = col & 127;
                    C[(((long long)b * NHn + h) * Tn + t) * KDn + kx] = v;
                }
            }
        }
    }
}

// ---------------- flash attention (tf32 mma, online softmax) ----------------
// grid (T/128, B*NH), 256 threads. Warp w owns Q rows [w*16, w*16+16) and their
// full softmax stats (warp-local shuffles only). K loop over 8 tiles of 64.
__global__ void __launch_bounds__(256, 1)
flash_attn(const float* __restrict__ Qg, const float* __restrict__ Kg,
           const float* __restrict__ Vg, float* __restrict__ Og)
{
    extern __shared__ float sm[];
    float (*Qs)[132] = (float(*)[132])sm;                                // 128x128 kd
    float (*Ks)[140] = (float(*)[140])(sm + 128*132);                    // 64 seq x 128 kd
    float (*Vs)[136] = (float(*)[136])(sm + 128*132 + 64*140);           // 64 seq x 128 kd
    float (*Ps)[76]  = (float(*)[76]) (sm + 128*132 + 64*140 + 64*136);  // 128 q x 64 seq

    int tid = threadIdx.x, lane = tid & 31, wid = tid >> 5;
    int g = lane >> 2, c = lane & 3;
    int bh  = blockIdx.y;
    int t0q = blockIdx.x << 7;
    const float scale = 0.08838834764831845f;   // 1/sqrt(128)

    const float* Qp = Qg + ((long long)bh * Tn + t0q) * KDn;
    const float* Kp = Kg + (long long)bh * Tn * KDn;
    const float* Vp = Vg + (long long)bh * Tn * KDn;

    // load Q tile (pre-scaled, tf32)
    for (int idx = tid; idx < 128 * 32; idx += 256) {
        int r = idx >> 5, k4 = (idx & 31) << 2;
        float4 qv = *(const float4*)&Qp[(long long)r * KDn + k4];
        Qs[r][k4+0] = to_tf32(qv.x * scale);
        Qs[r][k4+1] = to_tf32(qv.y * scale);
        Qs[r][k4+2] = to_tf32(qv.z * scale);
        Qs[r][k4+3] = to_tf32(qv.w * scale);
    }

    int wrow = wid << 4;
    float oacc[16][4];
    #pragma unroll
    for (int i = 0; i < 16; i++)
        oacc[i][0] = oacc[i][1] = oacc[i][2] = oacc[i][3] = 0.f;
    float m0 = -1e30f, m1 = -1e30f, l0 = 0.f, l1 = 0.f;

    for (int t0k = 0; t0k < Tn; t0k += 64) {
        __syncthreads();            // previous PV mma done reading Ks/Vs
        for (int idx = tid; idx < 64 * 32; idx += 256) {
            int r = idx >> 5, k4 = (idx & 31) << 2;
            float4 kv = *(const float4*)&Kp[(long long)(t0k + r) * KDn + k4];
            float4 vv = *(const float4*)&Vp[(long long)(t0k + r) * KDn + k4];
            Ks[r][k4+0] = to_tf32(kv.x); Ks[r][k4+1] = to_tf32(kv.y);
            Ks[r][k4+2] = to_tf32(kv.z); Ks[r][k4+3] = to_tf32(kv.w);
            Vs[r][k4+0] = to_tf32(vv.x); Vs[r][k4+1] = to_tf32(vv.y);
            Vs[r][k4+2] = to_tf32(vv.z); Vs[r][k4+3] = to_tf32(vv.w);
        }
        __syncthreads();

        // S = Q @ K^T for this warp's 16 rows x 64 cols
        float sacc[8][4] = {};
        #pragma unroll
        for (int kk = 0; kk < 128; kk += 8) {
            unsigned a0 = __float_as_uint(Qs[wrow + g    ][kk + c    ]);
            unsigned a1 = __float_as_uint(Qs[wrow + g + 8][kk + c    ]);
            unsigned a2 = __float_as_uint(Qs[wrow + g    ][kk + c + 4]);
            unsigned a3 = __float_as_uint(Qs[wrow + g + 8][kk + c + 4]);
            #pragma unroll
            for (int nt = 0; nt < 8; nt++) {
                int n = (nt << 3) + g;
                unsigned b0 = __float_as_uint(Ks[n][kk + c    ]);
                unsigned b1 = __float_as_uint(Ks[n][kk + c + 4]);
                mma_tf32(sacc[nt], a0, a1, a2, a3, b0, b1);
            }
        }

        // online softmax: thread holds rows {g, g+8}, cols {2c,2c+1} per ntile
        float rm0 = -1e30f, rm1 = -1e30f;
        #pragma unroll
        for (int nt = 0; nt < 8; nt++) {
            rm0 = fmaxf(rm0, fmaxf(sacc[nt][0], sacc[nt][1]));
            rm1 = fmaxf(rm1, fmaxf(sacc[nt][2], sacc[nt][3]));
        }
        rm0 = fmaxf(rm0, __shfl_xor_sync(0xffffffffu, rm0, 1));
        rm0 = fmaxf(rm0, __shfl_xor_sync(0xffffffffu, rm0, 2));
        rm1 = fmaxf(rm1, __shfl_xor_sync(0xffffffffu, rm1, 1));
        rm1 = fmaxf(rm1, __shfl_xor_sync(0xffffffffu, rm1, 2));
        float mn0 = fmaxf(m0, rm0), mn1 = fmaxf(m1, rm1);
        float cor0 = __expf(m0 - mn0), cor1 = __expf(m1 - mn1);
        float rs0 = 0.f, rs1 = 0.f;
        #pragma unroll
        for (int nt = 0; nt < 8; nt++) {
            float p0 = __expf(sacc[nt][0] - mn0);
            float p1 = __expf(sacc[nt][1] - mn0);
            float p2 = __expf(sacc[nt][2] - mn1);
            float p3 = __expf(sacc[nt][3] - mn1);
            rs0 += p0 + p1; rs1 += p2 + p3;
            int col = (nt << 3) + (c << 1);
            Ps[wrow + g    ][col]     = to_tf32(p0);
            Ps[wrow + g    ][col + 1] = to_tf32(p1);
            Ps[wrow + g + 8][col]     = to_tf32(p2);
            Ps[wrow + g + 8][col + 1] = to_tf32(p3);
        }
        rs0 += __shfl_xor_sync(0xffffffffu, rs0, 1);
        rs0 += __shfl_xor_sync(0xffffffffu, rs0, 2);
        rs1 += __shfl_xor_sync(0xffffffffu, rs1, 1);
        rs1 += __shfl_xor_sync(0xffffffffu, rs1, 2);
        l0 = l0 * cor0 + rs0; l1 = l1 * cor1 + rs1;
        m0 = mn0; m1 = mn1;
        #pragma unroll
        for (int nt = 0; nt < 16; nt++) {
            oacc[nt][0] *= cor0; oacc[nt][1] *= cor0;
            oacc[nt][2] *= cor1; oacc[nt][3] *= cor1;
        }
        __syncwarp();   // Ps rows are warp-private: warp-level ordering suffices

        // O += P @ V   (contraction over the 64 seq cols)
        #pragma unroll
        for (int kk = 0; kk < 64; kk += 8) {
            unsigned a0 = __float_as_uint(Ps[wrow + g    ][kk + c    ]);
            unsigned a1 = __float_as_uint(Ps[wrow + g + 8][kk + c    ]);
            unsigned a2 = __float_as_uint(Ps[wrow + g    ][kk + c + 4]);
            unsigned a3 = __float_as_uint(Ps[wrow + g + 8][kk + c + 4]);
            #pragma unroll
            for (int nt = 0; nt < 16; nt++) {
                int n = (nt << 3) + g;
                unsigned b0 = __float_as_uint(Vs[kk + c    ][n]);
                unsigned b1 = __float_as_uint(Vs[kk + c + 4][n]);
                mma_tf32(oacc[nt], a0, a1, a2, a3, b0, b1);
            }
        }
        __syncwarp();
    }

    // epilogue: divide by l, write O in [B,T,NH,KD]
    int b = bh >> 2, h = bh & 3;
    float inv0 = __fdividef(1.f, l0), inv1 = __fdividef(1.f, l1);
    int r0 = t0q + wrow + g, r1 = r0 + 8;
    long long base0 = (((long long)b * Tn + r0) * NHn + h) * KDn;
    long long base1 = (((long long)b * Tn + r1) * NHn + h) * KDn;
    #pragma unroll
    for (int nt = 0; nt < 16; nt++) {
        int col = (nt << 3) + (c << 1);
        Og[base0 + col]     = oacc[nt][0] * inv0;
        Og[base0 + col + 1] = oacc[nt][1] * inv0;
        Og[base1 + col]     = oacc[nt][2] * inv1;
        Og[base1 + col + 1] = oacc[nt][3] * inv1;
    }
}

// ---------------- persistent bidirectional GRU layer ----------------
// grid = B*2 CTAs; block = 384 threads; thread j owns gate column j,
// wh column cached in 128 registers. xv prefetched one step ahead.
__global__ void __launch_bounds__(384, 1)
gru_layer(const float* __restrict__ xgf, const float* __restrict__ xgb,
          const float* __restrict__ whf, const float* __restrict__ whb,
          const float* __restrict__ bhf, const float* __restrict__ bhb,
          float* __restrict__ yseq, float* __restrict__ hfin)
{
    int b   = blockIdx.x >> 1;
    int dir = blockIdx.x & 1;
    const float* xg = dir ? xgb : xgf;
    const float* wh = dir ? whb : whf;
    const float* bh = dir ? bhb : bhf;
    int j = threadIdx.x;

    __shared__ float4 h4s[32];       // hidden state h[128]
    __shared__ float  gate[256];     // z, r exchange
    float* h = (float*)h4s;

    float w[128];
    #pragma unroll
    for (int u = 0; u < 128; u++) w[u] = wh[u * Gn + j];
    float bj = bh[j];
    if (j < 128) h[j] = 0.f;
    __syncthreads();

    const float* xbase = xg + (long long)b * Tn * Gn;
    int t0 = dir ? (Tn - 1) : 0;
    float xv = xbase[(long long)t0 * Gn + j];

    for (int s = 0; s < Tn; s++) {
        int t  = dir ? (Tn - 1 - s) : s;
        int tn = dir ? (Tn - 2 - s) : (s + 1);
        float xv_next = (s + 1 < Tn) ? xbase[(long long)tn * Gn + j] : 0.f;

        float a0 = 0.f, a1 = 0.f, a2 = 0.f, a3 = 0.f;
        #pragma unroll
        for (int u = 0; u < 32; u++) {
            float4 hv = h4s[u];
            a0 = fmaf(hv.x, w[4 * u + 0], a0);
            a1 = fmaf(hv.y, w[4 * u + 1], a1);
            a2 = fmaf(hv.z, w[4 * u + 2], a2);
            a3 = fmaf(hv.w, w[4 * u + 3], a3);
        }
        float acc = (a0 + a1) + (a2 + a3) + bj;      // (h @ wh + bh)[j]
        if (j < 256)
            gate[j] = fsig(xv + acc);
        __syncthreads();
        if (j >= 256) {
            int u = j - 256;
            float r = gate[128 + u];
            float n = ftanh(xv + r * acc);
            float z = gate[u];
            float hn = z * h[u] + (1.f - z) * n;
            h[u] = hn;
            if (yseq)
                yseq[((long long)b * Tn + t) * Mn + dir * Un + u] = hn;
        }
        __syncthreads();
        xv = xv_next;
    }
    if (hfin && j < 128)
        hfin[b * Mn + dir * Un + j] = h[j];
}

// ---------------- final dense head [B,256] @ [256,1] ----------------
__global__ void dense_head(const float* __restrict__ h2, const float* __restrict__ w,
                           const float* __restrict__ bb, float* __restrict__ out)
{
    int b = blockIdx.x, tid = threadIdx.x;   // 256 threads
    __shared__ float red[256];
    red[tid] = h2[b * Mn + tid] * w[tid];
    __syncthreads();
    #pragma unroll
    for (int o = 128; o > 0; o >>= 1) {
        if (tid < o) red[tid] += red[tid + o];
        __syncthreads();
    }
    if (tid == 0) out[b] = red[0] + bb[0];
}

// ---------------- launch orchestration ----------------
extern "C" void kernel_launch(void* const* d_in, const int* in_sizes, int n_in,
                              void* d_out, int out_size)
{
    const float* inp     = (const float*)d_in[0];
    const float* conv_w  = (const float*)d_in[1];
    const float* conv_b  = (const float*)d_in[2];
    const float* bn_g    = (const float*)d_in[3];
    const float* bn_b    = (const float*)d_in[4];
    const float* bn_m    = (const float*)d_in[5];
    const float* bn_v    = (const float*)d_in[6];
    const float* g1f_wx  = (const float*)d_in[7];
    const float* g1f_wh  = (const float*)d_in[8];
    const float* g1f_b   = (const float*)d_in[9];
    const float* g1b_wx  = (const float*)d_in[10];
    const float* g1b_wh  = (const float*)d_in[11];
    const float* g1b_b   = (const float*)d_in[12];
    const float* wq      = (const float*)d_in[13];
    const float* bq      = (const float*)d_in[14];
    const float* wk      = (const float*)d_in[15];
    const float* bk      = (const float*)d_in[16];
    const float* wv      = (const float*)d_in[17];
    const float* bv      = (const float*)d_in[18];
    const float* wo      = (const float*)d_in[19];
    const float* bo      = (const float*)d_in[20];
    const float* g2f_wx  = (const float*)d_in[21];
    const float* g2f_wh  = (const float*)d_in[22];
    const float* g2f_b   = (const float*)d_in[23];
    const float* g2b_wx  = (const float*)d_in[24];
    const float* g2b_wh  = (const float*)d_in[25];
    const float* g2b_b   = (const float*)d_in[26];
    const float* dense_w = (const float*)d_in[27];
    const float* dense_b = (const float*)d_in[28];
    float* out = (float*)d_out;

    float *x1, *xgf, *xgb, *y1, *q, *k, *v, *o, *h2;
    cudaGetSymbolAddress((void**)&x1,  g_x1);
    cudaGetSymbolAddress((void**)&xgf, g_xgf);
    cudaGetSymbolAddress((void**)&xgb, g_xgb);
    cudaGetSymbolAddress((void**)&y1,  g_y1);
    cudaGetSymbolAddress((void**)&q,   g_q);
    cudaGetSymbolAddress((void**)&k,   g_k);
    cudaGetSymbolAddress((void**)&v,   g_v);
    cudaGetSymbolAddress((void**)&o,   g_o);
    cudaGetSymbolAddress((void**)&h2,  g_h2);

    // flash_attn needs ~173 KB dynamic smem (idempotent host call; not captured)
    const int FA_SMEM = (128*132 + 64*140 + 64*136 + 128*76) * 4;
    cudaFuncSetAttribute(flash_attn, cudaFuncAttributeMaxDynamicSharedMemorySize, FA_SMEM);

    dim3 blk(256);

    // 1) conv + BN + ReLU -> x1 [BT, F]
    conv_bn_relu<<<(BTn * Fn) / 256, 256>>>(inp, conv_w, conv_b, bn_g, bn_b, bn_m, bn_v);

    // 2) GRU1 input projections (f and b fused via grid.z)
    gemm_tf32<0><<<dim3(Gn/64, BTn/128, 2), blk>>>(
        x1, g1f_wx, g1b_wx, nullptr, xgf, xgb, nullptr,
        Gn, Fn, g1f_b, g1b_b, nullptr, nullptr);

    // 3) bidirectional GRU1 -> y1 [BT, 256]
    gru_layer<<<Bn * 2, 384>>>(xgf, xgb, g1f_wh, g1b_wh, g1f_b + Gn, g1b_b + Gn, y1, nullptr);

    // 4) QKV projections (single launch, grid.z=3) -> [B,NH,T,KD]
    gemm_tf32<1><<<dim3(512/64, BTn/128, 3), blk>>>(
        y1, wq, wk, wv, q, k, v,
        NHn*KDn, Mn, bq, bk, bv, nullptr);

    // 5-7) fused attention: scores + softmax + PV, out -> g_o [B,T,NH,KD]
    flash_attn<<<dim3(Tn/128, Bn*NHn), blk, FA_SMEM>>>(q, k, v, o);

    // 8) x2 = y1 + O @ wo + bo  -> k buffer [BT, 256]
    gemm_tf32<0><<<dim3(Mn/64, BTn/128, 1), blk>>>(
        o, wo, nullptr, nullptr, k, nullptr, nullptr,
        Mn, NHn*KDn, bo, nullptr, nullptr, y1);

    // 9) GRU2 input projections (f and b fused via grid.z)
    gemm_tf32<0><<<dim3(Gn/64, BTn/128, 2), blk>>>(
        k, g2f_wx, g2b_wx, nullptr, xgf, xgb, nullptr,
        Gn, Mn, g2f_b, g2b_b, nullptr, nullptr);

    // 10) bidirectional GRU2 (final states only) -> h2 [B, 256]
    gru_layer<<<Bn * 2, 384>>>(xgf, xgb, g2f_wh, g2b_wh, g2f_b + Gn, g2b_b + Gn, nullptr, h2);

    // 11) dense head -> out [B, 1]
    dense_head<<<Bn, 256>>>(h2, dense_w, dense_b, out);
}

// round 17
// speedup vs baseline: 1.1280x; 1.0620x over previous
#include <cuda_runtime.h>
#include <math.h>

// ---------------- problem constants ----------------
#define Bn   64
#define Tn   512
#define Dn   64
#define Fn   64
#define Un   128
#define Mn   256          // 2*U
#define NHn  4
#define KDn  128
#define Gn   384          // 3*U
#define BTn  (Bn*Tn)      // 32768

// ---------------- device scratch (no allocs allowed) ----------------
__device__ float g_x1 [BTn*Fn];             // conv output
__device__ float g_xgf[BTn*Gn];             // xg forward (reused)
__device__ float g_xgb[BTn*Gn];             // xg backward (reused)
__device__ float g_y1 [BTn*Mn];             // GRU1 sequence out
__device__ float g_q  [Bn*NHn*Tn*KDn];      // Q [B,NH,T,KD]
__device__ float g_k  [Bn*NHn*Tn*KDn];      // K / x2 [BT,M]
__device__ float g_v  [Bn*NHn*Tn*KDn];      // V
__device__ float g_o  [BTn*NHn*KDn];        // attention out [B,T,NH,KD]
__device__ float g_h2 [Bn*Mn];              // GRU2 final states

// ---------------- helpers ----------------
__device__ __forceinline__ float to_tf32(float x) {
    asm("cvt.rna.tf32.f32 %0, %0;" : "+f"(x));
    return x;
}
__device__ __forceinline__ void mma_tf32(float* d,
    unsigned a0, unsigned a1, unsigned a2, unsigned a3,
    unsigned b0, unsigned b1)
{
    asm volatile(
        "mma.sync.aligned.m16n8k8.row.col.f32.tf32.tf32.f32 "
        "{%0,%1,%2,%3}, {%4,%5,%6,%7}, {%8,%9}, {%0,%1,%2,%3};\n"
        : "+f"(d[0]), "+f"(d[1]), "+f"(d[2]), "+f"(d[3])
        : "r"(a0), "r"(a1), "r"(a2), "r"(a3), "r"(b0), "r"(b1));
}
__device__ __forceinline__ void ldsm4(unsigned& r0, unsigned& r1,
                                      unsigned& r2, unsigned& r3, unsigned addr)
{
    asm volatile("ldmatrix.sync.aligned.m8n8.x4.shared.b16 {%0,%1,%2,%3}, [%4];\n"
        : "=r"(r0), "=r"(r1), "=r"(r2), "=r"(r3) : "r"(addr));
}
__device__ __forceinline__ unsigned smem_u32(const void* p) {
    return (unsigned)__cvta_generic_to_shared(p);
}
__device__ __forceinline__ float fsig(float x) {
    x = fminf(fmaxf(x, -30.f), 30.f);
    return __fdividef(1.f, 1.f + __expf(-x));
}
__device__ __forceinline__ float ftanh(float x) {
    x = fminf(fmaxf(x, -15.f), 15.f);
    float e = __expf(2.f * x);
    return __fdividef(e - 1.f, e + 1.f);
}

// ---------------- conv1d(same,w=3) + BN(eps=1e-3) + ReLU ----------------
__global__ void conv_bn_relu(const float* __restrict__ x,
                             const float* __restrict__ w,
                             const float* __restrict__ cb,
                             const float* __restrict__ gamma,
                             const float* __restrict__ beta,
                             const float* __restrict__ mean,
                             const float* __restrict__ var)
{
    int idx = blockIdx.x * blockDim.x + threadIdx.x;
    if (idx >= BTn * Fn) return;
    int f = idx & 63;
    int t = (idx >> 6) & 511;
    int b = idx >> 15;
    float acc = cb[f];
    #pragma unroll
    for (int kk = 0; kk < 3; kk++) {
        int tt = t + kk - 1;
        if (tt < 0 || tt >= Tn) continue;
        const float* row = x + ((long long)b * Tn + tt) * Dn;
        const float* wr  = w + kk * Dn * Fn + f;
        #pragma unroll
        for (int d = 0; d < Dn; d++)
            acc = fmaf(row[d], wr[d * Fn], acc);
    }
    acc = (acc - mean[f]) * rsqrtf(var[f] + 1e-3f) * gamma[f] + beta[f];
    g_x1[idx] = fmaxf(acc, 0.f);
}

// ---------------- tf32 tensor-core GEMM, 128x128 tile, ldmatrix ----------------
// 256 threads = 8 warps in 2(m) x 4(n); warp tile 64x32 = 4x4 m16n8k8 tiles.
// Double-buffered smem, ONE __syncthreads per K-step (32 MMAs between barriers).
// A fragments via ldmatrix.x4 (pad-20 rows: 5-chunk stride covers all 8 chunk
// groups -> conflict-free LDSM). B scalar LDS on pad-136 (bank = 8c+g).
// grid.z selects among up to 3 (B, bias, C) sets so sibling GEMMs share a launch.
// EPI: 0 = plain row-major (+optional resid); 1 = QKV permute to [B,NH,T,KD].
template<int EPI>
__global__ void __launch_bounds__(256, 2)
gemm_tf32(const float* __restrict__ A,
          const float* B0, const float* B1, const float* B2,
          float* C0, float* C1, float* C2,
          int N, int K,
          const float* bias0, const float* bias1, const float* bias2,
          const float* __restrict__ resid)
{
    __shared__ float As[2][128][20];   // 20480 B
    __shared__ float Bs[2][16][136];   // 17408 B

    int z = blockIdx.z;
    const float* Bm   = (z == 0) ? B0 : (z == 1) ? B1 : B2;
    const float* bias = (z == 0) ? bias0 : (z == 1) ? bias1 : bias2;
    float*       C    = (z == 0) ? C0 : (z == 1) ? C1 : C2;

    int tid  = threadIdx.x;
    int lane = tid & 31;
    int wid  = tid >> 5;
    int wm   = wid >> 2;                 // 0..1 -> m offset wm*64
    int wn   = wid & 3;                  // 0..3 -> n offset wn*32
    int g    = lane >> 2;                // 0..7
    int c    = lane & 3;                 // 0..3
    int m0 = blockIdx.y << 7, n0 = blockIdx.x << 7;

    // ldmatrix per-lane address parts: lane l -> matrix mi = l>>3, row lr = l&7
    int mi = lane >> 3, lr = lane & 7;
    int arow = wm * 64 + (mi & 1) * 8 + lr;      // + mt*16 per use
    int acol = (mi >> 1) * 4;                    // + kk per use
    unsigned as_base = smem_u32(&As[0][0][0]);

    float acc[4][4][4] = {};                     // [mt][nt][i]

    int a_r = tid >> 2, a_c = (tid & 3) << 2;    // A: 64 rows x 16k per half
    int b_r = tid >> 5, b_c = (tid & 31) << 2;   // B: 8 rows x 128n per half

    const float* Ap0 = &A[(long long)(m0 + a_r) * K + a_c];
    const float* Ap1 = &A[(long long)(m0 + a_r + 64) * K + a_c];

    float4 ar0 = *(const float4*)Ap0;
    float4 ar1 = *(const float4*)Ap1;
    float4 br0 = *(const float4*)&Bm[(long long)b_r * N + n0 + b_c];
    float4 br1 = *(const float4*)&Bm[(long long)(b_r + 8) * N + n0 + b_c];

    int nk = K >> 4;
    for (int it = 0; it < nk; it++) {
        int pb = it & 1;
        float4 t0, t1, u0, u1;
        t0.x = to_tf32(ar0.x); t0.y = to_tf32(ar0.y); t0.z = to_tf32(ar0.z); t0.w = to_tf32(ar0.w);
        t1.x = to_tf32(ar1.x); t1.y = to_tf32(ar1.y); t1.z = to_tf32(ar1.z); t1.w = to_tf32(ar1.w);
        u0.x = to_tf32(br0.x); u0.y = to_tf32(br0.y); u0.z = to_tf32(br0.z); u0.w = to_tf32(br0.w);
        u1.x = to_tf32(br1.x); u1.y = to_tf32(br1.y); u1.z = to_tf32(br1.z); u1.w = to_tf32(br1.w);
        *(float4*)&As[pb][a_r     ][a_c] = t0;
        *(float4*)&As[pb][a_r + 64][a_c] = t1;
        *(float4*)&Bs[pb][b_r    ][b_c]  = u0;
        *(float4*)&Bs[pb][b_r + 8][b_c]  = u1;
        __syncthreads();

        if (it + 1 < nk) {
            int k0 = (it + 1) << 4;
            ar0 = *(const float4*)(Ap0 + k0);
            ar1 = *(const float4*)(Ap1 + k0);
            br0 = *(const float4*)&Bm[(long long)(k0 + b_r) * N + n0 + b_c];
            br1 = *(const float4*)&Bm[(long long)(k0 + b_r + 8) * N + n0 + b_c];
        }

        unsigned abase = as_base + (unsigned)(pb * 128 + arow) * 80u + (unsigned)acol * 4u;
        #pragma unroll
        for (int kk = 0; kk < 16; kk += 8) {
            unsigned af[4][4];
            #pragma unroll
            for (int mt = 0; mt < 4; mt++)
                ldsm4(af[mt][0], af[mt][1], af[mt][2], af[mt][3],
                      abase + (unsigned)(mt * 16 * 80 + kk * 4));
            #pragma unroll
            for (int nt = 0; nt < 4; nt++) {
                int ncol = wn * 32 + nt * 8 + g;
                unsigned b0 = __float_as_uint(Bs[pb][kk + c    ][ncol]);
                unsigned b1 = __float_as_uint(Bs[pb][kk + c + 4][ncol]);
                #pragma unroll
                for (int mt = 0; mt < 4; mt++)
                    mma_tf32(acc[mt][nt], af[mt][0], af[mt][1], af[mt][2], af[mt][3], b0, b1);
            }
        }
    }

    #pragma unroll
    for (int mt = 0; mt < 4; mt++) {
        #pragma unroll
        for (int nt = 0; nt < 4; nt++) {
            #pragma unroll
            for (int i = 0; i < 4; i++) {
                int row = m0 + wm * 64 + mt * 16 + g + ((i >> 1) << 3);
                int col = n0 + wn * 32 + nt * 8 + (c << 1) + (i & 1);
                float v = acc[mt][nt][i];
                if (bias) v += bias[col];
                if (EPI == 0) {
                    long long off = (long long)row * N + col;
                    if (resid) v += resid[off];
                    C[off] = v;
                } else {
                    int b = row >> 9, t = row & 511;
                    int h = col >> 7, kx = col & 127;
                    C[(((long long)b * NHn + h) * Tn + t) * KDn + kx] = v;
                }
            }
        }
    }
}

// ---------------- flash attention (tf32 mma, online softmax) ----------------
// grid (T/128, B*NH), 256 threads. Warp w owns Q rows [w*16, w*16+16) and their
// full softmax stats (warp-local shuffles only). K loop over 8 tiles of 64.
__global__ void __launch_bounds__(256, 1)
flash_attn(const float* __restrict__ Qg, const float* __restrict__ Kg,
           const float* __restrict__ Vg, float* __restrict__ Og)
{
    extern __shared__ float sm[];
    float (*Qs)[132] = (float(*)[132])sm;                                // 128x128 kd
    float (*Ks)[140] = (float(*)[140])(sm + 128*132);                    // 64 seq x 128 kd
    float (*Vs)[136] = (float(*)[136])(sm + 128*132 + 64*140);           // 64 seq x 128 kd
    float (*Ps)[76]  = (float(*)[76]) (sm + 128*132 + 64*140 + 64*136);  // 128 q x 64 seq

    int tid = threadIdx.x, lane = tid & 31, wid = tid >> 5;
    int g = lane >> 2, c = lane & 3;
    int bh  = blockIdx.y;
    int t0q = blockIdx.x << 7;
    const float scale = 0.08838834764831845f;   // 1/sqrt(128)

    const float* Qp = Qg + ((long long)bh * Tn + t0q) * KDn;
    const float* Kp = Kg + (long long)bh * Tn * KDn;
    const float* Vp = Vg + (long long)bh * Tn * KDn;

    // load Q tile (pre-scaled, tf32)
    for (int idx = tid; idx < 128 * 32; idx += 256) {
        int r = idx >> 5, k4 = (idx & 31) << 2;
        float4 qv = *(const float4*)&Qp[(long long)r * KDn + k4];
        Qs[r][k4+0] = to_tf32(qv.x * scale);
        Qs[r][k4+1] = to_tf32(qv.y * scale);
        Qs[r][k4+2] = to_tf32(qv.z * scale);
        Qs[r][k4+3] = to_tf32(qv.w * scale);
    }

    int wrow = wid << 4;
    float oacc[16][4];
    #pragma unroll
    for (int i = 0; i < 16; i++)
        oacc[i][0] = oacc[i][1] = oacc[i][2] = oacc[i][3] = 0.f;
    float m0 = -1e30f, m1 = -1e30f, l0 = 0.f, l1 = 0.f;

    for (int t0k = 0; t0k < Tn; t0k += 64) {
        __syncthreads();            // previous PV mma done reading Ks/Vs
        for (int idx = tid; idx < 64 * 32; idx += 256) {
            int r = idx >> 5, k4 = (idx & 31) << 2;
            float4 kv = *(const float4*)&Kp[(long long)(t0k + r) * KDn + k4];
            float4 vv = *(const float4*)&Vp[(long long)(t0k + r) * KDn + k4];
            Ks[r][k4+0] = to_tf32(kv.x); Ks[r][k4+1] = to_tf32(kv.y);
            Ks[r][k4+2] = to_tf32(kv.z); Ks[r][k4+3] = to_tf32(kv.w);
            Vs[r][k4+0] = to_tf32(vv.x); Vs[r][k4+1] = to_tf32(vv.y);
            Vs[r][k4+2] = to_tf32(vv.z); Vs[r][k4+3] = to_tf32(vv.w);
        }
        __syncthreads();

        // S = Q @ K^T for this warp's 16 rows x 64 cols
        float sacc[8][4] = {};
        #pragma unroll
        for (int kk = 0; kk < 128; kk += 8) {
            unsigned a0 = __float_as_uint(Qs[wrow + g    ][kk + c    ]);
            unsigned a1 = __float_as_uint(Qs[wrow + g + 8][kk + c    ]);
            unsigned a2 = __float_as_uint(Qs[wrow + g    ][kk + c + 4]);
            unsigned a3 = __float_as_uint(Qs[wrow + g + 8][kk + c + 4]);
            #pragma unroll
            for (int nt = 0; nt < 8; nt++) {
                int n = (nt << 3) + g;
                unsigned b0 = __float_as_uint(Ks[n][kk + c    ]);
                unsigned b1 = __float_as_uint(Ks[n][kk + c + 4]);
                mma_tf32(sacc[nt], a0, a1, a2, a3, b0, b1);
            }
        }

        // online softmax: thread holds rows {g, g+8}, cols {2c,2c+1} per ntile
        float rm0 = -1e30f, rm1 = -1e30f;
        #pragma unroll
        for (int nt = 0; nt < 8; nt++) {
            rm0 = fmaxf(rm0, fmaxf(sacc[nt][0], sacc[nt][1]));
            rm1 = fmaxf(rm1, fmaxf(sacc[nt][2], sacc[nt][3]));
        }
        rm0 = fmaxf(rm0, __shfl_xor_sync(0xffffffffu, rm0, 1));
        rm0 = fmaxf(rm0, __shfl_xor_sync(0xffffffffu, rm0, 2));
        rm1 = fmaxf(rm1, __shfl_xor_sync(0xffffffffu, rm1, 1));
        rm1 = fmaxf(rm1, __shfl_xor_sync(0xffffffffu, rm1, 2));
        float mn0 = fmaxf(m0, rm0), mn1 = fmaxf(m1, rm1);
        float cor0 = __expf(m0 - mn0), cor1 = __expf(m1 - mn1);
        float rs0 = 0.f, rs1 = 0.f;
        #pragma unroll
        for (int nt = 0; nt < 8; nt++) {
            float p0 = __expf(sacc[nt][0] - mn0);
            float p1 = __expf(sacc[nt][1] - mn0);
            float p2 = __expf(sacc[nt][2] - mn1);
            float p3 = __expf(sacc[nt][3] - mn1);
            rs0 += p0 + p1; rs1 += p2 + p3;
            int col = (nt << 3) + (c << 1);
            Ps[wrow + g    ][col]     = to_tf32(p0);
            Ps[wrow + g    ][col + 1] = to_tf32(p1);
            Ps[wrow + g + 8][col]     = to_tf32(p2);
            Ps[wrow + g + 8][col + 1] = to_tf32(p3);
        }
        rs0 += __shfl_xor_sync(0xffffffffu, rs0, 1);
        rs0 += __shfl_xor_sync(0xffffffffu, rs0, 2);
        rs1 += __shfl_xor_sync(0xffffffffu, rs1, 1);
        rs1 += __shfl_xor_sync(0xffffffffu, rs1, 2);
        l0 = l0 * cor0 + rs0; l1 = l1 * cor1 + rs1;
        m0 = mn0; m1 = mn1;
        #pragma unroll
        for (int nt = 0; nt < 16; nt++) {
            oacc[nt][0] *= cor0; oacc[nt][1] *= cor0;
            oacc[nt][2] *= cor1; oacc[nt][3] *= cor1;
        }
        __syncwarp();   // Ps rows are warp-private: warp-level ordering suffices

        // O += P @ V   (contraction over the 64 seq cols)
        #pragma unroll
        for (int kk = 0; kk < 64; kk += 8) {
            unsigned a0 = __float_as_uint(Ps[wrow + g    ][kk + c    ]);
            unsigned a1 = __float_as_uint(Ps[wrow + g + 8][kk + c    ]);
            unsigned a2 = __float_as_uint(Ps[wrow + g    ][kk + c + 4]);
            unsigned a3 = __float_as_uint(Ps[wrow + g + 8][kk + c + 4]);
            #pragma unroll
            for (int nt = 0; nt < 16; nt++) {
                int n = (nt << 3) + g;
                unsigned b0 = __float_as_uint(Vs[kk + c    ][n]);
                unsigned b1 = __float_as_uint(Vs[kk + c + 4][n]);
                mma_tf32(oacc[nt], a0, a1, a2, a3, b0, b1);
            }
        }
        __syncwarp();
    }

    // epilogue: divide by l, write O in [B,T,NH,KD]
    int b = bh >> 2, h = bh & 3;
    float inv0 = __fdividef(1.f, l0), inv1 = __fdividef(1.f, l1);
    int r0 = t0q + wrow + g, r1 = r0 + 8;
    long long base0 = (((long long)b * Tn + r0) * NHn + h) * KDn;
    long long base1 = (((long long)b * Tn + r1) * NHn + h) * KDn;
    #pragma unroll
    for (int nt = 0; nt < 16; nt++) {
        int col = (nt << 3) + (c << 1);
        Og[base0 + col]     = oacc[nt][0] * inv0;
        Og[base0 + col + 1] = oacc[nt][1] * inv0;
        Og[base1 + col]     = oacc[nt][2] * inv1;
        Og[base1 + col + 1] = oacc[nt][3] * inv1;
    }
}

// ---------------- persistent bidirectional GRU layer ----------------
// grid = B*2 CTAs; block = 384 threads; thread j owns gate column j,
// wh column cached in 128 registers. xv prefetched one step ahead.
__global__ void __launch_bounds__(384, 1)
gru_layer(const float* __restrict__ xgf, const float* __restrict__ xgb,
          const float* __restrict__ whf, const float* __restrict__ whb,
          const float* __restrict__ bhf, const float* __restrict__ bhb,
          float* __restrict__ yseq, float* __restrict__ hfin)
{
    int b   = blockIdx.x >> 1;
    int dir = blockIdx.x & 1;
    const float* xg = dir ? xgb : xgf;
    const float* wh = dir ? whb : whf;
    const float* bh = dir ? bhb : bhf;
    int j = threadIdx.x;

    __shared__ float4 h4s[32];       // hidden state h[128]
    __shared__ float  gate[256];     // z, r exchange
    float* h = (float*)h4s;

    float w[128];
    #pragma unroll
    for (int u = 0; u < 128; u++) w[u] = wh[u * Gn + j];
    float bj = bh[j];
    if (j < 128) h[j] = 0.f;
    __syncthreads();

    const float* xbase = xg + (long long)b * Tn * Gn;
    int t0 = dir ? (Tn - 1) : 0;
    float xv = xbase[(long long)t0 * Gn + j];

    for (int s = 0; s < Tn; s++) {
        int t  = dir ? (Tn - 1 - s) : s;
        int tn = dir ? (Tn - 2 - s) : (s + 1);
        float xv_next = (s + 1 < Tn) ? xbase[(long long)tn * Gn + j] : 0.f;

        float a0 = 0.f, a1 = 0.f, a2 = 0.f, a3 = 0.f;
        #pragma unroll
        for (int u = 0; u < 32; u++) {
            float4 hv = h4s[u];
            a0 = fmaf(hv.x, w[4 * u + 0], a0);
            a1 = fmaf(hv.y, w[4 * u + 1], a1);
            a2 = fmaf(hv.z, w[4 * u + 2], a2);
            a3 = fmaf(hv.w, w[4 * u + 3], a3);
        }
        float acc = (a0 + a1) + (a2 + a3) + bj;      // (h @ wh + bh)[j]
        if (j < 256)
            gate[j] = fsig(xv + acc);
        __syncthreads();
        if (j >= 256) {
            int u = j - 256;
            float r = gate[128 + u];
            float n = ftanh(xv + r * acc);
            float z = gate[u];
            float hn = z * h[u] + (1.f - z) * n;
            h[u] = hn;
            if (yseq)
                yseq[((long long)b * Tn + t) * Mn + dir * Un + u] = hn;
        }
        __syncthreads();
        xv = xv_next;
    }
    if (hfin && j < 128)
        hfin[b * Mn + dir * Un + j] = h[j];
}

// ---------------- final dense head [B,256] @ [256,1] ----------------
__global__ void dense_head(const float* __restrict__ h2, const float* __restrict__ w,
                           const float* __restrict__ bb, float* __restrict__ out)
{
    int b = blockIdx.x, tid = threadIdx.x;   // 256 threads
    __shared__ float red[256];
    red[tid] = h2[b * Mn + tid] * w[tid];
    __syncthreads();
    #pragma unroll
    for (int o = 128; o > 0; o >>= 1) {
        if (tid < o) red[tid] += red[tid + o];
        __syncthreads();
    }
    if (tid == 0) out[b] = red[0] + bb[0];
}

// ---------------- launch orchestration ----------------
extern "C" void kernel_launch(void* const* d_in, const int* in_sizes, int n_in,
                              void* d_out, int out_size)
{
    const float* inp     = (const float*)d_in[0];
    const float* conv_w  = (const float*)d_in[1];
    const float* conv_b  = (const float*)d_in[2];
    const float* bn_g    = (const float*)d_in[3];
    const float* bn_b    = (const float*)d_in[4];
    const float* bn_m    = (const float*)d_in[5];
    const float* bn_v    = (const float*)d_in[6];
    const float* g1f_wx  = (const float*)d_in[7];
    const float* g1f_wh  = (const float*)d_in[8];
    const float* g1f_b   = (const float*)d_in[9];
    const float* g1b_wx  = (const float*)d_in[10];
    const float* g1b_wh  = (const float*)d_in[11];
    const float* g1b_b   = (const float*)d_in[12];
    const float* wq      = (const float*)d_in[13];
    const float* bq      = (const float*)d_in[14];
    const float* wk      = (const float*)d_in[15];
    const float* bk      = (const float*)d_in[16];
    const float* wv      = (const float*)d_in[17];
    const float* bv      = (const float*)d_in[18];
    const float* wo      = (const float*)d_in[19];
    const float* bo      = (const float*)d_in[20];
    const float* g2f_wx  = (const float*)d_in[21];
    const float* g2f_wh  = (const float*)d_in[22];
    const float* g2f_b   = (const float*)d_in[23];
    const float* g2b_wx  = (const float*)d_in[24];
    const float* g2b_wh  = (const float*)d_in[25];
    const float* g2b_b   = (const float*)d_in[26];
    const float* dense_w = (const float*)d_in[27];
    const float* dense_b = (const float*)d_in[28];
    float* out = (float*)d_out;

    float *x1, *xgf, *xgb, *y1, *q, *k, *v, *o, *h2;
    cudaGetSymbolAddress((void**)&x1,  g_x1);
    cudaGetSymbolAddress((void**)&xgf, g_xgf);
    cudaGetSymbolAddress((void**)&xgb, g_xgb);
    cudaGetSymbolAddress((void**)&y1,  g_y1);
    cudaGetSymbolAddress((void**)&q,   g_q);
    cudaGetSymbolAddress((void**)&k,   g_k);
    cudaGetSymbolAddress((void**)&v,   g_v);
    cudaGetSymbolAddress((void**)&o,   g_o);
    cudaGetSymbolAddress((void**)&h2,  g_h2);

    // flash_attn needs ~173 KB dynamic smem (idempotent host call; not captured)
    const int FA_SMEM = (128*132 + 64*140 + 64*136 + 128*76) * 4;
    cudaFuncSetAttribute(flash_attn, cudaFuncAttributeMaxDynamicSharedMemorySize, FA_SMEM);

    dim3 blk(256);

    // 1) conv + BN + ReLU -> x1 [BT, F]
    conv_bn_relu<<<(BTn * Fn) / 256, 256>>>(inp, conv_w, conv_b, bn_g, bn_b, bn_m, bn_v);

    // 2) GRU1 input projections (f and b fused via grid.z)
    gemm_tf32<0><<<dim3(Gn/128, BTn/128, 2), blk>>>(
        x1, g1f_wx, g1b_wx, nullptr, xgf, xgb, nullptr,
        Gn, Fn, g1f_b, g1b_b, nullptr, nullptr);

    // 3) bidirectional GRU1 -> y1 [BT, 256]
    gru_layer<<<Bn * 2, 384>>>(xgf, xgb, g1f_wh, g1b_wh, g1f_b + Gn, g1b_b + Gn, y1, nullptr);

    // 4) QKV projections (single launch, grid.z=3) -> [B,NH,T,KD]
    gemm_tf32<1><<<dim3(512/128, BTn/128, 3), blk>>>(
        y1, wq, wk, wv, q, k, v,
        NHn*KDn, Mn, bq, bk, bv, nullptr);

    // 5-7) fused attention: scores + softmax + PV, out -> g_o [B,T,NH,KD]
    flash_attn<<<dim3(Tn/128, Bn*NHn), blk, FA_SMEM>>>(q, k, v, o);

    // 8) x2 = y1 + O @ wo + bo  -> k buffer [BT, 256]
    gemm_tf32<0><<<dim3(Mn/128, BTn/128, 1), blk>>>(
        o, wo, nullptr, nullptr, k, nullptr, nullptr,
        Mn, NHn*KDn, bo, nullptr, nullptr, y1);

    // 9) GRU2 input projections (f and b fused via grid.z)
    gemm_tf32<0><<<dim3(Gn/128, BTn/128, 2), blk>>>(
        k, g2f_wx, g2b_wx, nullptr, xgf, xgb, nullptr,
        Gn, Mn, g2f_b, g2b_b, nullptr, nullptr);

    // 10) bidirectional GRU2 (final states only) -> h2 [B, 256]
    gru_layer<<<Bn * 2, 384>>>(xgf, xgb, g2f_wh, g2b_wh, g2f_b + Gn, g2b_b + Gn, nullptr, h2);

    // 11) dense head -> out [B, 1]
    dense_head<<<Bn, 256>>>(h2, dense_w, dense_b, out);
}